// round 15
// baseline (speedup 1.0000x reference)
#include <cuda_runtime.h>
#include <cuda_fp16.h>
#include <math.h>

#define NA 4096
#define NB 4096
#define NS 4
#define BK 512                     // K-tile columns
#define NTILE (4096 / BK)          // 8
#define NBUF 4                     // pipeline depth (3 tiles in flight)
#define KSTRIDE (BK + 8)           // padded halves per K-tile row (520)

// Scratch (device globals — allocation-free per harness rules)
__device__ __half g_Kh [(size_t)NA * NB];   // K[n][m]  = exp(-C[n][m]/eps), fp16
__device__ __half g_KTh[(size_t)NB * NA];   // KT[m][n] = K[n][m], fp16
__device__ float  g_u  [NS * NA];           // u, fp32, s-major
__device__ float  g_v  [NS * NB];           // v, fp32, s-major
__device__ __half g_uh [NS * NA];           // fp16(u * 2^16)  (B operand image)
__device__ __half g_vh [NS * NB];           // fp16(v)         (B operand image)

// ---------------------------------------------------------------------------
// cp.async helpers
// ---------------------------------------------------------------------------
__device__ __forceinline__ void cp_async16(unsigned saddr, const void* gptr) {
    asm volatile("cp.async.cg.shared.global [%0], [%1], 16;\n"
                 :: "r"(saddr), "l"(gptr));
}
__device__ __forceinline__ void cp_commit() {
    asm volatile("cp.async.commit_group;\n");
}
template <int N>
__device__ __forceinline__ void cp_wait() {
    asm volatile("cp.async.wait_group %0;\n" :: "n"(N));
}

__device__ __forceinline__ uint2 pack4h(float a, float b, float c, float d) {
    __half2 lo = __floats2half2_rn(a, b);
    __half2 hi = __floats2half2_rn(c, d);
    uint2 r;
    r.x = *(unsigned*)&lo;
    r.y = *(unsigned*)&hi;
    return r;
}

// ---------------------------------------------------------------------------
// Kernel 1: K = exp(-C/eps) (fp16) and its transpose.
// 64(cols) x 32(rows) tile, 256 threads, float4 loads, 8B packed stores.
// ---------------------------------------------------------------------------
__global__ void __launch_bounds__(256) expT_kernel(const float* __restrict__ C,
                                                   const float* __restrict__ eps_p) {
    __shared__ float tt[64][33];              // [col][row], padded
    const float scale = -1.44269504088896340736f / eps_p[0];
    const int bx = blockIdx.x * 64;           // column base
    const int by = blockIdx.y * 32;           // row base
    const int tid = threadIdx.x;
    const int c4 = tid & 15;
    const int r  = tid >> 4;

#pragma unroll
    for (int j = 0; j < 2; ++j) {
        const int row = r + j * 16;
        const float4 cv = *(const float4*)&C[(size_t)(by + row) * NB + bx + c4 * 4];
        const float e0 = exp2f(cv.x * scale);
        const float e1 = exp2f(cv.y * scale);
        const float e2 = exp2f(cv.z * scale);
        const float e3 = exp2f(cv.w * scale);
        *(uint2*)&g_Kh[(size_t)(by + row) * NB + bx + c4 * 4] = pack4h(e0, e1, e2, e3);
        tt[c4 * 4 + 0][row] = e0;
        tt[c4 * 4 + 1][row] = e1;
        tt[c4 * 4 + 2][row] = e2;
        tt[c4 * 4 + 3][row] = e3;
    }
    __syncthreads();

    const int rg  = tid & 7;
    const int tc_ = tid >> 3;
#pragma unroll
    for (int j = 0; j < 2; ++j) {
        const int tc = tc_ + j * 32;
        const float f0 = tt[tc][rg * 4 + 0];
        const float f1 = tt[tc][rg * 4 + 1];
        const float f2 = tt[tc][rg * 4 + 2];
        const float f3 = tt[tc][rg * 4 + 3];
        *(uint2*)&g_KTh[(size_t)(bx + tc) * NA + by + rg * 4] = pack4h(f0, f1, f2, f3);
    }
}

__global__ void init_v_kernel() {
    const int i = blockIdx.x * blockDim.x + threadIdx.x;
    if (i < NS * NB) { g_v[i] = 1.0f; g_vh[i] = __float2half_rn(1.0f); }
}

// ---------------------------------------------------------------------------
// Kernel 3: one Sinkhorn half-step via HMMA m16n8k16.
//   dir=0: u = alpha / (K  v)    reads g_vh (= fp16 v), writes g_u + g_uh
//   dir=1: v = beta  / (KT u)    reads g_uh (= fp16 u*2^16), writes g_v + g_vh
// Block = 16 rows, 256 threads / 8 warps; K via 4-deep cp.async pipeline.
// B frags read DIRECTLY from the global fp16 x image (L1/L2 resident, 32KB) —
// no per-block staging, no converts, no smem x.
// ---------------------------------------------------------------------------
__global__ void __launch_bounds__(256) phase_kernel(const int dir,
                                                    const float* __restrict__ tgt) {
    extern __shared__ __half sk[];                     // NBUF * 16 * KSTRIDE
    float* sred = (float*)(sk + NBUF * 16 * KSTRIDE);  // 8 * 64 floats

    const __half* __restrict__ M  = dir ? g_KTh : g_Kh;
    const __half* __restrict__ xh = dir ? g_uh  : g_vh;
    float*        __restrict__ out  = dir ? g_v  : g_u;
    __half*       __restrict__ outh = dir ? g_vh : g_uh;
    const float sc_in    = dir ? 65536.0f : 1.0f;   // scale baked into xh
    const float sc_store = dir ? 1.0f : 65536.0f;   // scale for produced image

    const int tid  = threadIdx.x;
    const int warp = tid >> 5;
    const int lane = tid & 31;
    const int row0b = blockIdx.x * 16;
    const __half* __restrict__ Mrow = M + (size_t)row0b * 4096;

    const unsigned sk_base = (unsigned)__cvta_generic_to_shared(sk);
#define ISSUE_TILE(t)                                                          \
    {                                                                          \
        const __half* gb = Mrow + (t) * BK;                                    \
        const unsigned bb = sk_base + ((t) % NBUF) * (16 * KSTRIDE * 2);       \
        _Pragma("unroll")                                                      \
        for (int g = tid; g < 1024; g += 256) {                                \
            const int r = g >> 6, c8 = (g & 63) << 3;                          \
            cp_async16(bb + (unsigned)(r * KSTRIDE + c8) * 2,                  \
                       gb + (size_t)r * 4096 + c8);                            \
        }                                                                      \
        cp_commit();                                                           \
    }

    ISSUE_TILE(0);
    ISSUE_TILE(1);
    ISSUE_TILE(2);

    // C fragment (f32): c0,c1 -> row lane/4, cols (lane%4)*2,+1
    //                   c2,c3 -> row lane/4+8, same cols
    float c0 = 0.f, c1 = 0.f, c2 = 0.f, c3 = 0.f;

    // ldmatrix lane-address precompute (within a tile buffer)
    const int lm_row = (lane & 7) + ((lane >> 3) & 1) * 8;
    const int lm_kof = (lane >> 4) * 8;

    // B-frag source (global): s = lane>>2 (valid if <4), k-pair (lane&3)*2
    const int bs   = lane >> 2;
    const bool bok = bs < NS;
    const __half* __restrict__ bx = xh + bs * 4096 + (lane & 3) * 2;

#pragma unroll
    for (int t = 0; t < NTILE; ++t) {
        // Wait for tile t. Pending groups: 3 while issuing continues.
        if      (t <= NTILE - 3) cp_wait<2>();
        else if (t == NTILE - 2) cp_wait<1>();
        else                     cp_wait<0>();
        __syncthreads();   // tile t visible to all warps

        if (t + 3 < NTILE) ISSUE_TILE(t + 3);   // prefetch before compute

        const __half* kb = sk + (t % NBUF) * 16 * KSTRIDE;

#pragma unroll
        for (int j = 0; j < 4; ++j) {
            const int kloc = warp * 64 + j * 16;        // k16-step in tile
            unsigned a0, a1, a2, a3;
            {
                const __half* ap = kb + lm_row * KSTRIDE + kloc + lm_kof;
                const unsigned aaddr = (unsigned)__cvta_generic_to_shared(ap);
                asm volatile(
                    "ldmatrix.sync.aligned.m8n8.x4.shared.b16 {%0,%1,%2,%3}, [%4];"
                    : "=r"(a0), "=r"(a1), "=r"(a2), "=r"(a3) : "r"(aaddr));
            }
            const int gk = t * BK + kloc;
            unsigned b0 = 0, b1 = 0;
            if (bok) {
                b0 = *(const unsigned*)(bx + gk);       // LDG, L1-resident
                b1 = *(const unsigned*)(bx + gk + 8);
            }
            asm volatile(
                "mma.sync.aligned.m16n8k16.row.col.f32.f16.f16.f32 "
                "{%0,%1,%2,%3}, {%4,%5,%6,%7}, {%8,%9}, {%0,%1,%2,%3};"
                : "+f"(c0), "+f"(c1), "+f"(c2), "+f"(c3)
                : "r"(a0), "r"(a1), "r"(a2), "r"(a3), "r"(b0), "r"(b1));
        }
        __syncthreads();   // all reads of buffer (t%NBUF) done before reuse
    }

    // Publish per-warp partial C tiles (only cols 0..3 = s are meaningful)
    if ((lane & 3) < 2) {
        const int r  = lane >> 2;
        const int cc = (lane & 3) * 2;
        float* sw = sred + warp * 64;        // [16 rows][4 s]
        sw[r * 4 + cc]           = c0;
        sw[r * 4 + cc + 1]       = c1;
        sw[(r + 8) * 4 + cc]     = c2;
        sw[(r + 8) * 4 + cc + 1] = c3;
    }
    __syncthreads();

    // Combine 8 warps: 64 threads, one output each.
    // out = tgt * sc_in / sum ; also emit the pre-scaled fp16 image.
    if (tid < 64) {
        const int row = tid >> 2;
        const int s   = tid & 3;
        float sum = 0.f;
#pragma unroll
        for (int w = 0; w < 8; ++w) sum += sred[w * 64 + row * 4 + s];
        const float val = tgt[s * 4096 + row0b + row] * sc_in / sum;
        out [s * 4096 + row0b + row] = val;
        outh[s * 4096 + row0b + row] = __float2half_rn(val * sc_store);
    }
#undef ISSUE_TILE
}

// ---------------------------------------------------------------------------
// Kernel 4: f = eps*log(u), g = eps*log(v)
// ---------------------------------------------------------------------------
__global__ void finalize_kernel(const float* __restrict__ eps_p,
                                float* __restrict__ out) {
    const int i = blockIdx.x * blockDim.x + threadIdx.x;
    const float eps = eps_p[0];
    if (i < NS * NA) {
        out[i]           = eps * logf(g_u[i]);
        out[i + NS * NA] = eps * logf(g_v[i]);
    }
}

// ---------------------------------------------------------------------------
extern "C" void kernel_launch(void* const* d_in, const int* in_sizes, int n_in,
                              void* d_out, int out_size) {
    const float* alpha = (const float*)d_in[0];   // (4, 4096)
    const float* beta  = (const float*)d_in[1];   // (4, 4096)
    const float* C     = (const float*)d_in[2];   // (4096, 4096)
    const float* eps   = (const float*)d_in[3];   // scalar
    float* out = (float*)d_out;                   // f (4,4096) then g (4,4096)

    const int smem = NBUF * 16 * KSTRIDE * (int)sizeof(__half)
                   + 8 * 64 * (int)sizeof(float);   // ~67.1 KB
    cudaFuncSetAttribute(phase_kernel,
                         cudaFuncAttributeMaxDynamicSharedMemorySize, smem);

    expT_kernel<<<dim3(NB / 64, NA / 32), 256>>>(C, eps);
    init_v_kernel<<<(NS * NB + 1023) / 1024, 1024>>>();

    for (int it = 0; it < 10; ++it) {
        phase_kernel<<<256, 256, smem>>>(0, alpha);  // u = alpha/(K v)
        phase_kernel<<<256, 256, smem>>>(1, beta);   // v = beta /(KT u)
    }

    finalize_kernel<<<(NS * NA + 255) / 256, 256>>>(eps, out);
}

// round 16
// speedup vs baseline: 1.6028x; 1.6028x over previous
#include <cuda_runtime.h>
#include <cuda_fp16.h>
#include <math.h>

#define NA 4096
#define NB 4096
#define NS 4
#define BK 512                     // K-tile columns
#define NTILE (4096 / BK)          // 8
#define NBUF 4                     // pipeline depth (3 tiles in flight)
#define KSTRIDE (BK + 8)           // padded halves per K-tile row (520)
#define XSTRIDE (4096 + 16)        // padded halves per x row (4112)

// Scratch (device globals — allocation-free per harness rules)
__device__ __half g_Kh [(size_t)NA * NB];   // K[n][m]  = exp(-C[n][m]/eps), fp16
__device__ __half g_KTh[(size_t)NB * NA];   // KT[m][n] = K[n][m], fp16
__device__ float  g_u  [NS * NA];           // u, fp32, s-major
__device__ float  g_v  [NS * NB];           // v, fp32, s-major
__device__ __half g_uh [NS * NA];           // fp16(u * 2^16)  (B operand image)
__device__ __half g_vh [NS * NB];           // fp16(v)         (B operand image)

// ---------------------------------------------------------------------------
// cp.async helpers
// ---------------------------------------------------------------------------
__device__ __forceinline__ void cp_async16(unsigned saddr, const void* gptr) {
    asm volatile("cp.async.cg.shared.global [%0], [%1], 16;\n"
                 :: "r"(saddr), "l"(gptr));
}
__device__ __forceinline__ void cp_commit() {
    asm volatile("cp.async.commit_group;\n");
}
template <int N>
__device__ __forceinline__ void cp_wait() {
    asm volatile("cp.async.wait_group %0;\n" :: "n"(N));
}

__device__ __forceinline__ uint2 pack4h(float a, float b, float c, float d) {
    __half2 lo = __floats2half2_rn(a, b);
    __half2 hi = __floats2half2_rn(c, d);
    uint2 r;
    r.x = *(unsigned*)&lo;
    r.y = *(unsigned*)&hi;
    return r;
}

// ---------------------------------------------------------------------------
// Kernel 1: K = exp(-C/eps) (fp16) and its transpose.
// 64(cols) x 32(rows) tile, 256 threads, float4 loads, 8B packed stores.
// ---------------------------------------------------------------------------
__global__ void __launch_bounds__(256) expT_kernel(const float* __restrict__ C,
                                                   const float* __restrict__ eps_p) {
    __shared__ float tt[64][33];              // [col][row], padded
    const float scale = -1.44269504088896340736f / eps_p[0];
    const int bx = blockIdx.x * 64;           // column base
    const int by = blockIdx.y * 32;           // row base
    const int tid = threadIdx.x;
    const int c4 = tid & 15;
    const int r  = tid >> 4;

#pragma unroll
    for (int j = 0; j < 2; ++j) {
        const int row = r + j * 16;
        const float4 cv = *(const float4*)&C[(size_t)(by + row) * NB + bx + c4 * 4];
        const float e0 = exp2f(cv.x * scale);
        const float e1 = exp2f(cv.y * scale);
        const float e2 = exp2f(cv.z * scale);
        const float e3 = exp2f(cv.w * scale);
        *(uint2*)&g_Kh[(size_t)(by + row) * NB + bx + c4 * 4] = pack4h(e0, e1, e2, e3);
        tt[c4 * 4 + 0][row] = e0;
        tt[c4 * 4 + 1][row] = e1;
        tt[c4 * 4 + 2][row] = e2;
        tt[c4 * 4 + 3][row] = e3;
    }
    __syncthreads();

    const int rg  = tid & 7;
    const int tc_ = tid >> 3;
#pragma unroll
    for (int j = 0; j < 2; ++j) {
        const int tc = tc_ + j * 32;
        const float f0 = tt[tc][rg * 4 + 0];
        const float f1 = tt[tc][rg * 4 + 1];
        const float f2 = tt[tc][rg * 4 + 2];
        const float f3 = tt[tc][rg * 4 + 3];
        *(uint2*)&g_KTh[(size_t)(bx + tc) * NA + by + rg * 4] = pack4h(f0, f1, f2, f3);
    }
}

__global__ void init_v_kernel() {
    const int i = blockIdx.x * blockDim.x + threadIdx.x;
    if (i < NS * NB) { g_v[i] = 1.0f; g_vh[i] = __float2half_rn(1.0f); }
}

// ---------------------------------------------------------------------------
// Kernel 3: one Sinkhorn half-step via HMMA m16n8k16.
//   dir=0: u = alpha / (K  v)    reads g_vh (fp16 v),       writes g_u + g_uh
//   dir=1: v = beta  / (KT u)    reads g_uh (fp16 u*2^16),  writes g_v + g_vh
// Block = 16 rows, 256 threads / 8 warps; K via 4-deep cp.async pipeline.
// x staged into padded smem by a raw 32KB cp.async copy of the fp16 image,
// committed WITH tile 0 (overlaps the first DMA; zero converts on consumer).
// B frags via conflict-free LDS from padded smem (the proven R14 path).
// ---------------------------------------------------------------------------
__global__ void __launch_bounds__(256) phase_kernel(const int dir,
                                                    const float* __restrict__ tgt) {
    extern __shared__ __half sh[];
    __half* sx = sh;                                   // NS * XSTRIDE halves
    __half* sk = sh + NS * XSTRIDE;                    // NBUF * 16 * KSTRIDE
    float*  sred = (float*)(sk + NBUF * 16 * KSTRIDE); // 8 * 64 floats

    const __half* __restrict__ M  = dir ? g_KTh : g_Kh;
    const __half* __restrict__ xh = dir ? g_uh  : g_vh;
    float*        __restrict__ out  = dir ? g_v  : g_u;
    __half*       __restrict__ outh = dir ? g_vh : g_uh;
    const float sc_in    = dir ? 65536.0f : 1.0f;   // scale baked into xh
    const float sc_store = dir ? 1.0f : 65536.0f;   // scale for produced image

    const int tid  = threadIdx.x;
    const int warp = tid >> 5;
    const int lane = tid & 31;
    const int row0b = blockIdx.x * 16;
    const __half* __restrict__ Mrow = M + (size_t)row0b * 4096;

    const unsigned sk_base = (unsigned)__cvta_generic_to_shared(sk);
    const unsigned sx_base = (unsigned)__cvta_generic_to_shared(sx);

#define ISSUE_TILE_BODY(t)                                                     \
    {                                                                          \
        const __half* gb = Mrow + (t) * BK;                                    \
        const unsigned bb = sk_base + ((t) % NBUF) * (16 * KSTRIDE * 2);       \
        _Pragma("unroll")                                                      \
        for (int g = tid; g < 1024; g += 256) {                                \
            const int r = g >> 6, c8 = (g & 63) << 3;                          \
            cp_async16(bb + (unsigned)(r * KSTRIDE + c8) * 2,                  \
                       gb + (size_t)r * 4096 + c8);                            \
        }                                                                      \
    }

    // x copy (fp16 image -> padded smem): 2048 16B chunks, 8/thread.
    // Committed together with tile 0 so both drain at the first wait.
    {
#pragma unroll
        for (int g = tid; g < 2048; g += 256) {
            const int s = g >> 9, c8 = (g & 511) << 3;   // 512 chunks per s
            cp_async16(sx_base + (unsigned)(s * XSTRIDE + c8) * 2,
                       xh + (size_t)s * 4096 + c8);
        }
        ISSUE_TILE_BODY(0);
        cp_commit();                 // group: {x, tile0}
        ISSUE_TILE_BODY(1); cp_commit();
        ISSUE_TILE_BODY(2); cp_commit();
    }

    // C fragment (f32): c0,c1 -> row lane/4, cols (lane%4)*2,+1
    //                   c2,c3 -> row lane/4+8, same cols
    float c0 = 0.f, c1 = 0.f, c2 = 0.f, c3 = 0.f;

    // ldmatrix lane-address precompute (within a tile buffer)
    const int lm_row = (lane & 7) + ((lane >> 3) & 1) * 8;
    const int lm_kof = (lane >> 4) * 8;

    // B-frag source (smem): s = lane>>2 (valid if <4), k-pair (lane&3)*2
    const int bs   = lane >> 2;
    const bool bok = bs < NS;
    const __half* __restrict__ bx = sx + bs * XSTRIDE + (lane & 3) * 2;

#pragma unroll
    for (int t = 0; t < NTILE; ++t) {
        // Pending groups before wait: min(3, NTILE-t). Drain down to tile t.
        if      (t <= NTILE - 3) cp_wait<2>();
        else if (t == NTILE - 2) cp_wait<1>();
        else                     cp_wait<0>();
        __syncthreads();   // tile t (and x, at t=0) visible to all warps

        if (t + 3 < NTILE) { ISSUE_TILE_BODY(t + 3); cp_commit(); }

        const __half* kb = sk + (t % NBUF) * 16 * KSTRIDE;

#pragma unroll
        for (int j = 0; j < 4; ++j) {
            const int kloc = warp * 64 + j * 16;        // k16-step in tile
            unsigned a0, a1, a2, a3;
            {
                const __half* ap = kb + lm_row * KSTRIDE + kloc + lm_kof;
                const unsigned aaddr = (unsigned)__cvta_generic_to_shared(ap);
                asm volatile(
                    "ldmatrix.sync.aligned.m8n8.x4.shared.b16 {%0,%1,%2,%3}, [%4];"
                    : "=r"(a0), "=r"(a1), "=r"(a2), "=r"(a3) : "r"(aaddr));
            }
            const int gk = t * BK + kloc;
            unsigned b0 = 0, b1 = 0;
            if (bok) {
                b0 = *(const unsigned*)(bx + gk);       // LDS.32, bank-safe
                b1 = *(const unsigned*)(bx + gk + 8);
            }
            asm volatile(
                "mma.sync.aligned.m16n8k16.row.col.f32.f16.f16.f32 "
                "{%0,%1,%2,%3}, {%4,%5,%6,%7}, {%8,%9}, {%0,%1,%2,%3};"
                : "+f"(c0), "+f"(c1), "+f"(c2), "+f"(c3)
                : "r"(a0), "r"(a1), "r"(a2), "r"(a3), "r"(b0), "r"(b1));
        }
        __syncthreads();   // all reads of buffer (t%NBUF) done before reuse
    }

    // Publish per-warp partial C tiles (only cols 0..3 = s are meaningful)
    if ((lane & 3) < 2) {
        const int r  = lane >> 2;
        const int cc = (lane & 3) * 2;
        float* sw = sred + warp * 64;        // [16 rows][4 s]
        sw[r * 4 + cc]           = c0;
        sw[r * 4 + cc + 1]       = c1;
        sw[(r + 8) * 4 + cc]     = c2;
        sw[(r + 8) * 4 + cc + 1] = c3;
    }
    __syncthreads();

    // Combine 8 warps: 64 threads, one output each.
    // out = tgt * sc_in / sum ; also emit the pre-scaled fp16 image.
    if (tid < 64) {
        const int row = tid >> 2;
        const int s   = tid & 3;
        float sum = 0.f;
#pragma unroll
        for (int w = 0; w < 8; ++w) sum += sred[w * 64 + row * 4 + s];
        const float val = tgt[s * 4096 + row0b + row] * sc_in / sum;
        out [s * 4096 + row0b + row] = val;
        outh[s * 4096 + row0b + row] = __float2half_rn(val * sc_store);
    }
#undef ISSUE_TILE_BODY
}

// ---------------------------------------------------------------------------
// Kernel 4: f = eps*log(u), g = eps*log(v)
// ---------------------------------------------------------------------------
__global__ void finalize_kernel(const float* __restrict__ eps_p,
                                float* __restrict__ out) {
    const int i = blockIdx.x * blockDim.x + threadIdx.x;
    const float eps = eps_p[0];
    if (i < NS * NA) {
        out[i]           = eps * logf(g_u[i]);
        out[i + NS * NA] = eps * logf(g_v[i]);
    }
}

// ---------------------------------------------------------------------------
extern "C" void kernel_launch(void* const* d_in, const int* in_sizes, int n_in,
                              void* d_out, int out_size) {
    const float* alpha = (const float*)d_in[0];   // (4, 4096)
    const float* beta  = (const float*)d_in[1];   // (4, 4096)
    const float* C     = (const float*)d_in[2];   // (4096, 4096)
    const float* eps   = (const float*)d_in[3];   // scalar
    float* out = (float*)d_out;                   // f (4,4096) then g (4,4096)

    const int smem = (NS * XSTRIDE + NBUF * 16 * KSTRIDE) * (int)sizeof(__half)
                   + 8 * 64 * (int)sizeof(float);   // ~101.4 KB
    cudaFuncSetAttribute(phase_kernel,
                         cudaFuncAttributeMaxDynamicSharedMemorySize, smem);

    expT_kernel<<<dim3(NB / 64, NA / 32), 256>>>(C, eps);
    init_v_kernel<<<(NS * NB + 1023) / 1024, 1024>>>();

    for (int it = 0; it < 10; ++it) {
        phase_kernel<<<256, 256, smem>>>(0, alpha);  // u = alpha/(K v)
        phase_kernel<<<256, 256, smem>>>(1, beta);   // v = beta /(KT u)
    }

    finalize_kernel<<<(NS * NA + 255) / 256, 256>>>(eps, out);
}